// round 12
// baseline (speedup 1.0000x reference)
#include <cuda_runtime.h>
#include <cstdint>
#include <math_constants.h>

// Sampler: penalties + temperature + top-k/top-p mask + gumbel sample + top-L logprobs.
//
// R12 vs R11: row is split across NPART=4 independent CTAs of 256 threads
// (grid 512) + a small merge kernel (grid 128). Rationale: R11 falsified the
// MLP theory (DRAM% unchanged); limiter is the single synchronized 1024-thread
// CTA per SM (all warps stall at each barrier, 20 SMs idle). Smaller
// independent part-CTAs (5 resident/SM) overlap each other's latency phases
// and use all 148 SMs. Pass-1 inner loop reverted to the R10 8-elem shape.
//
// Exactness: per part, theta = bin-floor of the 64th-largest of 256 per-thread
// maxima <= part's 64th-largest element (disjoint coverage), so each part's
// exact top-64 is recovered; global top-64 is a subset of the union of part
// top-64s (parts disjoint). S = sum of per-part partial sums in fixed order.

#define NT1      256
#define NPART    4
#define SHIFT    20
#define HB       4096          // ordered-float bins: ordf(x) >> 20
#define PCAP     1536
#define HASH_SZ  512
#define BMW1     1024          // part bitmap words: Vp <= 32768
#define WPT1     (BMW1 / NT1)  // 4
#define MAXCH    128           // Vp/256 <= 128
#define MAXB     256
#define NT2      256
#define BIG_NEG  (-1e30f)
#define SAMP_EPS 1e-5f

// cross-kernel scratch (no allocations allowed)
__device__ float g_pV[MAXB * NPART * 64];
__device__ int   g_pI[MAXB * NPART * 64];
__device__ int   g_pN[MAXB * NPART];
__device__ float g_pS[MAXB * NPART];

__device__ __forceinline__ unsigned ordf(float x) {
    unsigned u = __float_as_uint(x);
    return (u & 0x80000000u) ? ~u : (u | 0x80000000u);
}

__device__ __forceinline__ int hlookup(const int* hkey, const int* hcnt, int tok) {
    unsigned slot = ((unsigned)tok * 2654435761u) & (HASH_SZ - 1);
    while (true) {
        int k = hkey[slot];
        if (k == tok) return hcnt[slot];
        if (k == -1)  return 0;
        slot = (slot + 1) & (HASH_SZ - 1);
    }
}

// Full reference-order transform for a special (bitmap-marked) token:
// stop-min (if needed) -> repetition (if prompt/output member) -> freq/presence
// (if output member) -> temperature. v is the GLOBAL token id.
__device__ __forceinline__ float spec_val(float x, int v, bool need,
    int s0, int s1, int s2, int s3, const int* stopPenSh,
    float rp, float fp, float pp, float invt,
    const int* hkey, const int* hcnt)
{
    bool penal = true;
    if (need) {
        int which = (v == s0) ? 0 : (v == s1) ? 1 : (v == s2) ? 2 : (v == s3) ? 3 : -1;
        if (which >= 0) {
            penal = stopPenSh[which] != 0;   // was it in prompt|output?
            x = fminf(x, BIG_NEG);
        }
    }
    if (penal) {
        x = (x > 0.0f) ? (x / rp) : (x * rp);
        int c = hlookup(hkey, hcnt, v);
        if (c > 0) x -= fp * (float)c + pp;
    }
    return x * invt;
}

// ================= KERNEL A: one CTA per (part, row) =================
__global__ __launch_bounds__(NT1, 5) void part_kernel(
    const float* __restrict__ logits,
    const int*   __restrict__ prompt_ids,
    const int*   __restrict__ output_ids,
    const int*   __restrict__ stop_ids,
    const int*   __restrict__ min_tokens,
    const float* __restrict__ presence,
    const float* __restrict__ frequency,
    const float* __restrict__ repetition,
    const float* __restrict__ temperature,
    int B, int V, int P, int O, int S, int Vp)
{
    __shared__ unsigned bm[BMW1];              // 4KB: part-local membership bitmap
    __shared__ int   hkey[HASH_SZ];            // output-count hash, GLOBAL token keys
    __shared__ int   hcnt[HASH_SZ];
    __shared__ int   scratch[HB];              // 16KB overlay: hist -> candV/candI
    int*   hist  = scratch;
    float* candV = reinterpret_cast<float*>(scratch);
    int*   candI = scratch + PCAP;
    __shared__ float chunkMax[MAXCH];
    __shared__ int   flagged[MAXCH];
    __shared__ float sortedV[64];
    __shared__ int   sortedI[64];
    __shared__ float redf[NT1 / 32];
    __shared__ int   stopPenSh[4];
    __shared__ int   shCand, shNFlag, shQHead;
    __shared__ float shS, shTheta;

    const int p   = blockIdx.x;
    const int b   = blockIdx.y;
    const int tid = threadIdx.x;
    const int lane = tid & 31;
    const int wid  = tid >> 5;
    const int partBase = p * Vp;
    const int partEnd  = partBase + Vp;
    const int nChunk = Vp >> 8;                 // 256-elem chunks

    // ---- init shared ----
    for (int i = tid; i < BMW1; i += NT1) bm[i] = 0u;
    for (int i = tid; i < HB;   i += NT1) hist[i] = 0;
    for (int i = tid; i < HASH_SZ; i += NT1) { hkey[i] = -1; hcnt[i] = 0; }
    if (tid == 0) { shCand = 0; shNFlag = 0; shQHead = 0; }
    __syncthreads();

    // ---- row params ----
    const bool  need = min_tokens[b] > O;
    const float rp = repetition[b], fp = frequency[b], pp = presence[b];
    const float traw = temperature[b];
    const float t = (traw < SAMP_EPS) ? 1.0f : traw;
    const float invt = 1.0f / t;
    const int s0 = (S > 0) ? stop_ids[(size_t)b * S + 0] : -1;
    const int s1 = (S > 1) ? stop_ids[(size_t)b * S + 1] : -1;
    const int s2 = (S > 2) ? stop_ids[(size_t)b * S + 2] : -1;
    const int s3 = (S > 3) ? stop_ids[(size_t)b * S + 3] : -1;

    // ---- build membership bitmap + output counts (range-filtered) ----
    for (int i = tid; i < O; i += NT1) {
        int tok = output_ids[(size_t)b * O + i];
        if (tok >= partBase && tok < partEnd) {
            atomicOr(&bm[(tok - partBase) >> 5], 1u << (tok & 31));
            unsigned slot = ((unsigned)tok * 2654435761u) & (HASH_SZ - 1);
            while (true) {
                int old = atomicCAS(&hkey[slot], -1, tok);
                if (old == -1 || old == tok) { atomicAdd(&hcnt[slot], 1); break; }
                slot = (slot + 1) & (HASH_SZ - 1);
            }
        }
    }
    for (int i = tid; i < P; i += NT1) {
        int tok = prompt_ids[(size_t)b * P + i];
        if (tok >= partBase && tok < partEnd)
            atomicOr(&bm[(tok - partBase) >> 5], 1u << (tok & 31));
    }
    __syncthreads();

    // ---- fold in-range stop tokens into bitmap (recording prior membership) ----
    if (tid == 0 && need) {
        int ss[4] = {s0, s1, s2, s3};
        int pen[4];
        #pragma unroll
        for (int k = 0; k < 4; k++) {
            bool inr = (ss[k] >= partBase && ss[k] < partEnd);
            pen[k] = inr ? (int)((bm[(ss[k] - partBase) >> 5] >> (ss[k] & 31)) & 1u) : 1;
        }
        #pragma unroll
        for (int k = 0; k < 4; k++) {
            stopPenSh[k] = pen[k];
            if (ss[k] >= partBase && ss[k] < partEnd)
                bm[(ss[k] - partBase) >> 5] |= 1u << (ss[k] & 31);
        }
    }
    __syncthreads();

    const float* lpart = logits + (size_t)b * V + partBase;

    // ===== PASS 1: thread max + exp-sum + chunk maxes (local indices) =====
    float mx = -CUDART_INF_F;
    float s  = 0.0f;
    for (int it = 0; ; ++it) {
        const int chunk = (it << 3) + wid;          // 8 warps, warp-uniform
        if (chunk >= nChunk) break;
        const int base = (chunk << 8) + (lane << 3);
        float4 q0 = *reinterpret_cast<const float4*>(lpart + base);
        float4 q1 = *reinterpret_cast<const float4*>(lpart + base + 4);
        unsigned w = bm[base >> 5];
        const int sh = base & 31;
        float xs[8] = {q0.x, q0.y, q0.z, q0.w, q1.x, q1.y, q1.z, q1.w};
        float im = -CUDART_INF_F;
        #pragma unroll
        for (int j = 0; j < 8; j++) {
            float x = ((w >> (sh + j)) & 1u) ? -CUDART_INF_F : xs[j] * invt;
            im = fmaxf(im, x);
            s += __expf(x);                          // exp(-inf) = 0 for masked
        }
        mx = fmaxf(mx, im);
        float cm = im;
        #pragma unroll
        for (int o = 16; o; o >>= 1) cm = fmaxf(cm, __shfl_xor_sync(0xffffffffu, cm, o));
        if (lane == 0) chunkMax[chunk] = cm;
    }

    // ---- specials phase A: fold transformed values into thread max + exp-sum ----
    #pragma unroll
    for (int k = 0; k < WPT1; k++) {
        int wi = tid * WPT1 + k;
        unsigned w = bm[wi];
        int baseTok = wi << 5;
        while (w) {
            int bpos = __ffs(w) - 1; w &= (w - 1);
            int vl = baseTok + bpos;                 // local index
            float x = spec_val(lpart[vl], partBase + vl, need, s0, s1, s2, s3,
                               stopPenSh, rp, fp, pp, invt, hkey, hcnt);
            mx = fmaxf(mx, x);
            s += __expf(x);
        }
    }

    // histogram of the 256 thread-maxes; warp partial sums
    atomicAdd(&hist[ordf(mx) >> SHIFT], 1);
    float ws = s;
    #pragma unroll
    for (int o = 16; o; o >>= 1) ws += __shfl_xor_sync(0xffffffffu, ws, o);
    if (lane == 0) redf[wid] = ws;
    __syncthreads();                                 // hist + redf + chunkMax complete

    if (tid == 0) {                                  // final exp-sum (8 warps)
        float v = 0.0f;
        #pragma unroll
        for (int i = 0; i < NT1 / 32; i++) v += redf[i];
        shS = v;
    }
    if (wid == 1) {                                  // theta: cum-from-top >= 64
        int running = 0;
        for (int base = HB - 1; base >= 0; base -= 32) {
            int bin = base - lane;                   // lane 0 = highest bin
            int cnt = (bin >= 0) ? hist[bin] : 0;
            int pref = cnt;
            #pragma unroll
            for (int o = 1; o < 32; o <<= 1) {
                int nv = __shfl_up_sync(0xffffffffu, pref, o);
                if (lane >= o) pref += nv;
            }
            int tot = __shfl_sync(0xffffffffu, pref, 31);
            if (running + tot >= 64) {
                unsigned msk = __ballot_sync(0xffffffffu, running + pref >= 64);
                int Lm = __ffs(msk) - 1;
                int bstar = base - Lm;
                if (bstar < 0) bstar = 0;
                if (lane == 0) {
                    unsigned tu = (unsigned)bstar << SHIFT;   // bin lower edge
                    float th;
                    if (tu == 0u)               th = -CUDART_INF_F;
                    else if (tu & 0x80000000u)  th = __uint_as_float(tu ^ 0x80000000u);
                    else                        th = __uint_as_float(~tu);
                    shTheta = th;
                }
                break;
            }
            running += tot;
        }
    }
    __syncthreads();
    const float theta = shTheta;

    // ---- flag chunks that can contain a candidate ----
    if (tid < nChunk && chunkMax[tid] >= theta) {
        int q = atomicAdd(&shNFlag, 1);
        flagged[q] = tid;
    }
    __syncthreads();
    const int nFlag = shNFlag;

    // ===== PASS 2: candidates only, flagged chunks via work queue (L2) =====
    while (true) {
        int mc;
        if (lane == 0) mc = atomicAdd(&shQHead, 1);
        mc = __shfl_sync(0xffffffffu, mc, 0);
        if (mc >= nFlag) break;
        const int c = flagged[mc];
        const int base = (c << 8) + (lane << 3);
        float4 q0 = *reinterpret_cast<const float4*>(lpart + base);
        float4 q1 = *reinterpret_cast<const float4*>(lpart + base + 4);
        unsigned w = bm[base >> 5];
        const int sh = base & 31;
        float xs[8] = {q0.x, q0.y, q0.z, q0.w, q1.x, q1.y, q1.z, q1.w};
        #pragma unroll
        for (int j = 0; j < 8; j++) {
            if (!((w >> (sh + j)) & 1u)) {
                float x = xs[j] * invt;
                if (x >= theta) {
                    int q = atomicAdd(&shCand, 1);
                    if (q < PCAP) { candV[q] = x; candI[q] = partBase + base + j; }
                }
            }
        }
    }
    // specials phase B: candidate test
    #pragma unroll
    for (int k = 0; k < WPT1; k++) {
        int wi = tid * WPT1 + k;
        unsigned w = bm[wi];
        int baseTok = wi << 5;
        while (w) {
            int bpos = __ffs(w) - 1; w &= (w - 1);
            int vl = baseTok + bpos;
            float x = spec_val(lpart[vl], partBase + vl, need, s0, s1, s2, s3,
                               stopPenSh, rp, fp, pp, invt, hkey, hcnt);
            if (x >= theta) {
                int q = atomicAdd(&shCand, 1);
                if (q < PCAP) { candV[q] = x; candI[q] = partBase + vl; }
            }
        }
    }
    __syncthreads();

    // ---- exact rank sort of part candidates (value desc, index asc) ----
    const int C = min(shCand, PCAP);
    const int Ntop = min(64, C);
    for (int i = tid; i < C; i += NT1) {
        float vi = candV[i]; int ii = candI[i];
        int r = 0;
        for (int j = 0; j < C; j++) {
            float vj = candV[j];
            if (vj > vi || (vj == vi && candI[j] < ii)) r++;
        }
        if (r < 64) { sortedV[r] = vi; sortedI[r] = ii; }
    }
    __syncthreads();

    // ---- emit part top-64 + partial sum ----
    const int gbase = (b * NPART + p) * 64;
    if (tid < Ntop) { g_pV[gbase + tid] = sortedV[tid]; g_pI[gbase + tid] = sortedI[tid]; }
    if (tid == 0)   { g_pN[b * NPART + p] = Ntop; g_pS[b * NPART + p] = shS; }
}

// ================= KERNEL B: merge parts + epilogue, one CTA per row =================
__global__ __launch_bounds__(NT2) void merge_kernel(
    const float* __restrict__ temperature,
    const int*   __restrict__ top_k,
    const float* __restrict__ top_p,
    const float* __restrict__ noise,
    float*       __restrict__ out,
    int B, int V, int L)
{
    __shared__ float mV[NPART * 64];
    __shared__ int   mI[NPART * 64];
    __shared__ float sortedV[64];
    __shared__ int   sortedI[64];
    __shared__ float scoreV[64];
    __shared__ int   shNkept;
    __shared__ float shS, shLse;

    const int b   = blockIdx.x;
    const int tid = threadIdx.x;

    const float traw = temperature[b];
    const float t = (traw < SAMP_EPS) ? 1.0f : traw;
    const float invt = 1.0f / t;

    // load 4x64 part candidates
    {
        const int pp_ = tid >> 6, sl = tid & 63;
        const int n = g_pN[b * NPART + pp_];
        if (sl < n) {
            mV[tid] = g_pV[(b * NPART + pp_) * 64 + sl];
            mI[tid] = g_pI[(b * NPART + pp_) * 64 + sl];
        } else {
            mV[tid] = -CUDART_INF_F;
            mI[tid] = 0x7F000000 + tid;              // unique, sorts last
        }
    }
    __syncthreads();

    // rank-merge 256 -> top 64 (value desc, index asc)
    {
        float vi = mV[tid]; int ii = mI[tid];
        int r = 0;
        for (int j = 0; j < NPART * 64; j++) {
            float vj = mV[j];
            if (vj > vi || (vj == vi && mI[j] < ii)) r++;
        }
        if (r < 64) { sortedV[r] = vi; sortedI[r] = ii; }
    }
    __syncthreads();

    // ---- prefix top-k & top-p (exclusive cumsum, strict <), masked LSE ----
    if (tid == 0) {
        float Sall = 0.0f;
        #pragma unroll
        for (int p2 = 0; p2 < NPART; p2++) Sall += g_pS[b * NPART + p2];
        shS = Sall;
        int totalN = 0;
        #pragma unroll
        for (int p2 = 0; p2 < NPART; p2++) totalN += g_pN[b * NPART + p2];
        const int Ntop = min(64, totalN);
        int ke = top_k[b]; if (ke < 1) ke = V;
        const float tp = top_p[b];
        float c = 0.0f; int nk = 0;
        for (int i = 0; i < Ntop; i++) {
            if (i < ke && c < tp) { nk = i + 1; c += expf(sortedV[i]) / Sall; }
            else break;
        }
        float sum = 0.0f;
        for (int i = 0; i < nk; i++) sum += expf(sortedV[i]);
        shLse = logf(sum);
        shNkept = nk;
    }
    __syncthreads();
    const int nk = shNkept;
    const float lse = shLse;

    // ---- gumbel scores over kept set (parallel noise gather) ----
    if (tid < nk) {
        int idx = sortedI[tid];
        float u = noise[(size_t)b * V + idx];
        float g = -logf(-logf(u));
        scoreV[tid] = sortedV[tid] * invt + g;
    }
    __syncthreads();
    if (tid == 0) {
        int best;
        if (traw < SAMP_EPS) {
            best = sortedI[0];                       // greedy: ties -> lowest index
        } else {
            best = sortedI[0]; float bs = scoreV[0];
            for (int i = 1; i < nk; i++) {
                float sc = scoreV[i]; int ix = sortedI[i];
                if (sc > bs || (sc == bs && ix < best)) { bs = sc; best = ix; }
            }
        }
        out[b] = (float)best;
    }

    // ---- top-L logprobs + indices ----
    float* lpOut = out + B + (size_t)b * L;
    float* ixOut = out + B + (size_t)B * L + (size_t)b * L;
    if (tid < L) {
        if (tid < nk) {
            lpOut[tid] = sortedV[tid] - lse;
            ixOut[tid] = (float)sortedI[tid];
        } else {
            lpOut[tid] = BIG_NEG;                    // exact: -1e30 - lse == -1e30 in f32
        }
    }
    // fill remaining index slots with the smallest non-kept token ids
    // (lax.top_k tie-break: ascending index among equal BIG_NEG values)
    const int needFill = L - nk;
    if (needFill > 0 && tid < 192) {
        int cid = tid;
        bool inKept = false; int less = 0;
        for (int i = 0; i < nk; i++) {
            int si = sortedI[i];
            inKept |= (si == cid);
            less += (si < cid);
        }
        if (!inKept) {
            int rank = cid - less;                   // rank among non-kept ids
            if (rank < needFill) ixOut[nk + rank] = (float)cid;
        }
    }
}

extern "C" void kernel_launch(void* const* d_in, const int* in_sizes, int n_in,
                              void* d_out, int out_size) {
    const float* logits  = (const float*)d_in[0];
    const int*   prompt  = (const int*)  d_in[1];
    const int*   outtok  = (const int*)  d_in[2];
    const int*   stoptok = (const int*)  d_in[3];
    const int*   mintok  = (const int*)  d_in[4];
    const float* pres    = (const float*)d_in[5];
    const float* freq    = (const float*)d_in[6];
    const float* rep     = (const float*)d_in[7];
    const float* temp    = (const float*)d_in[8];
    const int*   topk    = (const int*)  d_in[9];
    const float* topp    = (const float*)d_in[10];
    const float* noise   = (const float*)d_in[11];

    const int B = in_sizes[4];
    const int V = in_sizes[0] / B;
    const int P = in_sizes[1] / B;
    const int O = in_sizes[2] / B;
    const int S = in_sizes[3] / B;
    const int L = (out_size / B - 1) / 2;   // [sampled(B), logprobs(B,L), indices(B,L)]
    const int Vp = V / NPART;               // 32000 for V=128000 (multiple of 256)

    dim3 gridA(NPART, B);
    part_kernel<<<gridA, NT1>>>(logits, prompt, outtok, stoptok, mintok,
                                pres, freq, rep, temp, B, V, P, O, S, Vp);
    merge_kernel<<<B, NT2>>>(temp, topk, topp, noise, (float*)d_out, B, V, L);
}

// round 13
// speedup vs baseline: 1.0570x; 1.0570x over previous
#include <cuda_runtime.h>
#include <cstdint>
#include <math_constants.h>

// Sampler: penalties + temperature + top-k/top-p mask + gumbel sample + top-L logprobs.
//
// R13 vs R12: the separate merge kernel (measured 25.7us, occ 12%, almost all
// launch/serial overhead) is fused into the part kernel via a last-CTA-done
// handoff (threadfence + atomic counter per row). The last part-CTA of each row
// performs the 4x64 rank-merge + epilogue, overlapped with other rows' part
// scans. Part-scan math identical to R12 (passed, rel_err ~1e-36).
//
// Exactness: per part, theta = bin-floor of the 64th-largest of 256 per-thread
// maxima <= part's 64th-largest element (disjoint coverage), so each part's
// exact top-64 is recovered; global top-64 c union of part top-64s (parts
// disjoint). S = sum of per-part partial sums in fixed order. Merge result
// depends only on final scratch state -> deterministic regardless of arrival
// order. Counter reset by the merging CTA keeps the kernel graph-replayable.

#define NT1      256
#define NPART    4
#define SHIFT    20
#define HB       4096          // ordered-float bins: ordf(x) >> 20
#define PCAP     1536
#define HASH_SZ  512
#define BMW1     1024          // part bitmap words: Vp <= 32768
#define WPT1     (BMW1 / NT1)  // 4
#define MAXCH    128           // Vp/256 <= 128
#define MAXB     256
#define BIG_NEG  (-1e30f)
#define SAMP_EPS 1e-5f

// cross-CTA scratch (no allocations allowed)
__device__ float g_pV[MAXB * NPART * 64];
__device__ int   g_pI[MAXB * NPART * 64];
__device__ int   g_pN[MAXB * NPART];
__device__ float g_pS[MAXB * NPART];
__device__ int   g_cnt[MAXB];              // zero-initialized; reset after each merge

__device__ __forceinline__ unsigned ordf(float x) {
    unsigned u = __float_as_uint(x);
    return (u & 0x80000000u) ? ~u : (u | 0x80000000u);
}

__device__ __forceinline__ int hlookup(const int* hkey, const int* hcnt, int tok) {
    unsigned slot = ((unsigned)tok * 2654435761u) & (HASH_SZ - 1);
    while (true) {
        int k = hkey[slot];
        if (k == tok) return hcnt[slot];
        if (k == -1)  return 0;
        slot = (slot + 1) & (HASH_SZ - 1);
    }
}

// Full reference-order transform for a special (bitmap-marked) token:
// stop-min (if needed) -> repetition (if prompt/output member) -> freq/presence
// (if output member) -> temperature. v is the GLOBAL token id.
__device__ __forceinline__ float spec_val(float x, int v, bool need,
    int s0, int s1, int s2, int s3, const int* stopPenSh,
    float rp, float fp, float pp, float invt,
    const int* hkey, const int* hcnt)
{
    bool penal = true;
    if (need) {
        int which = (v == s0) ? 0 : (v == s1) ? 1 : (v == s2) ? 2 : (v == s3) ? 3 : -1;
        if (which >= 0) {
            penal = stopPenSh[which] != 0;   // was it in prompt|output?
            x = fminf(x, BIG_NEG);
        }
    }
    if (penal) {
        x = (x > 0.0f) ? (x / rp) : (x * rp);
        int c = hlookup(hkey, hcnt, v);
        if (c > 0) x -= fp * (float)c + pp;
    }
    return x * invt;
}

// ================= fused kernel: one CTA per (part, row); last CTA merges =================
__global__ __launch_bounds__(NT1, 5) void sampler_kernel(
    const float* __restrict__ logits,
    const int*   __restrict__ prompt_ids,
    const int*   __restrict__ output_ids,
    const int*   __restrict__ stop_ids,
    const int*   __restrict__ min_tokens,
    const float* __restrict__ presence,
    const float* __restrict__ frequency,
    const float* __restrict__ repetition,
    const float* __restrict__ temperature,
    const int*   __restrict__ top_k,
    const float* __restrict__ top_p,
    const float* __restrict__ noise,
    float*       __restrict__ out,
    int B, int V, int P, int O, int S, int L, int Vp)
{
    __shared__ unsigned bm[BMW1];              // 4KB: part-local membership bitmap
    __shared__ int   hkey[HASH_SZ];            // output-count hash, GLOBAL token keys
    __shared__ int   hcnt[HASH_SZ];
    __shared__ int   scratch[HB];              // 16KB overlay: hist -> candV/candI -> merge
    int*   hist  = scratch;
    float* candV = reinterpret_cast<float*>(scratch);
    int*   candI = scratch + PCAP;
    float* mV    = reinterpret_cast<float*>(scratch);           // merge phase
    int*   mI    = scratch + NPART * 64;
    float* eV    = reinterpret_cast<float*>(scratch + 2 * NPART * 64);
    __shared__ float chunkMax[MAXCH];
    __shared__ int   flagged[MAXCH];
    __shared__ float sortedV[64];
    __shared__ int   sortedI[64];
    __shared__ float scoreV[64];
    __shared__ float redf[NT1 / 32];
    __shared__ int   stopPenSh[4];
    __shared__ int   shCand, shNFlag, shQHead, shLast, shNkept;
    __shared__ float shS, shTheta, shLse;

    const int p   = blockIdx.x;
    const int b   = blockIdx.y;
    const int tid = threadIdx.x;
    const int lane = tid & 31;
    const int wid  = tid >> 5;
    const int partBase = p * Vp;
    const int partEnd  = partBase + Vp;
    const int nChunk = Vp >> 8;                 // 256-elem chunks

    // ---- init shared ----
    for (int i = tid; i < BMW1; i += NT1) bm[i] = 0u;
    for (int i = tid; i < HB;   i += NT1) hist[i] = 0;
    for (int i = tid; i < HASH_SZ; i += NT1) { hkey[i] = -1; hcnt[i] = 0; }
    if (tid == 0) { shCand = 0; shNFlag = 0; shQHead = 0; }
    __syncthreads();

    // ---- row params ----
    const bool  need = min_tokens[b] > O;
    const float rp = repetition[b], fp = frequency[b], pp = presence[b];
    const float traw = temperature[b];
    const float t = (traw < SAMP_EPS) ? 1.0f : traw;
    const float invt = 1.0f / t;
    const int s0 = (S > 0) ? stop_ids[(size_t)b * S + 0] : -1;
    const int s1 = (S > 1) ? stop_ids[(size_t)b * S + 1] : -1;
    const int s2 = (S > 2) ? stop_ids[(size_t)b * S + 2] : -1;
    const int s3 = (S > 3) ? stop_ids[(size_t)b * S + 3] : -1;

    // ---- build membership bitmap + output counts (range-filtered) ----
    for (int i = tid; i < O; i += NT1) {
        int tok = output_ids[(size_t)b * O + i];
        if (tok >= partBase && tok < partEnd) {
            atomicOr(&bm[(tok - partBase) >> 5], 1u << (tok & 31));
            unsigned slot = ((unsigned)tok * 2654435761u) & (HASH_SZ - 1);
            while (true) {
                int old = atomicCAS(&hkey[slot], -1, tok);
                if (old == -1 || old == tok) { atomicAdd(&hcnt[slot], 1); break; }
                slot = (slot + 1) & (HASH_SZ - 1);
            }
        }
    }
    for (int i = tid; i < P; i += NT1) {
        int tok = prompt_ids[(size_t)b * P + i];
        if (tok >= partBase && tok < partEnd)
            atomicOr(&bm[(tok - partBase) >> 5], 1u << (tok & 31));
    }
    __syncthreads();

    // ---- fold in-range stop tokens into bitmap (recording prior membership) ----
    if (tid == 0 && need) {
        int ss[4] = {s0, s1, s2, s3};
        int pen[4];
        #pragma unroll
        for (int k = 0; k < 4; k++) {
            bool inr = (ss[k] >= partBase && ss[k] < partEnd);
            pen[k] = inr ? (int)((bm[(ss[k] - partBase) >> 5] >> (ss[k] & 31)) & 1u) : 1;
        }
        #pragma unroll
        for (int k = 0; k < 4; k++) {
            stopPenSh[k] = pen[k];
            if (ss[k] >= partBase && ss[k] < partEnd)
                bm[(ss[k] - partBase) >> 5] |= 1u << (ss[k] & 31);
        }
    }
    __syncthreads();

    const float* lpart = logits + (size_t)b * V + partBase;

    // ===== PASS 1: thread max + exp-sum + chunk maxes (local indices) =====
    float mx = -CUDART_INF_F;
    float s  = 0.0f;
    for (int it = 0; ; ++it) {
        const int chunk = (it << 3) + wid;          // 8 warps, warp-uniform
        if (chunk >= nChunk) break;
        const int base = (chunk << 8) + (lane << 3);
        float4 q0 = *reinterpret_cast<const float4*>(lpart + base);
        float4 q1 = *reinterpret_cast<const float4*>(lpart + base + 4);
        unsigned w = bm[base >> 5];
        const int sh = base & 31;
        float xs[8] = {q0.x, q0.y, q0.z, q0.w, q1.x, q1.y, q1.z, q1.w};
        float im = -CUDART_INF_F;
        #pragma unroll
        for (int j = 0; j < 8; j++) {
            float x = ((w >> (sh + j)) & 1u) ? -CUDART_INF_F : xs[j] * invt;
            im = fmaxf(im, x);
            s += __expf(x);                          // exp(-inf) = 0 for masked
        }
        mx = fmaxf(mx, im);
        float cm = im;
        #pragma unroll
        for (int o = 16; o; o >>= 1) cm = fmaxf(cm, __shfl_xor_sync(0xffffffffu, cm, o));
        if (lane == 0) chunkMax[chunk] = cm;
    }

    // ---- specials phase A: fold transformed values into thread max + exp-sum ----
    #pragma unroll
    for (int k = 0; k < WPT1; k++) {
        int wi = tid * WPT1 + k;
        unsigned w = bm[wi];
        int baseTok = wi << 5;
        while (w) {
            int bpos = __ffs(w) - 1; w &= (w - 1);
            int vl = baseTok + bpos;                 // local index
            float x = spec_val(lpart[vl], partBase + vl, need, s0, s1, s2, s3,
                               stopPenSh, rp, fp, pp, invt, hkey, hcnt);
            mx = fmaxf(mx, x);
            s += __expf(x);
        }
    }

    // histogram of the 256 thread-maxes; warp partial sums
    atomicAdd(&hist[ordf(mx) >> SHIFT], 1);
    float ws = s;
    #pragma unroll
    for (int o = 16; o; o >>= 1) ws += __shfl_xor_sync(0xffffffffu, ws, o);
    if (lane == 0) redf[wid] = ws;
    __syncthreads();                                 // hist + redf + chunkMax complete

    if (tid == 0) {                                  // final exp-sum (8 warps)
        float v = 0.0f;
        #pragma unroll
        for (int i = 0; i < NT1 / 32; i++) v += redf[i];
        shS = v;
    }
    if (wid == 1) {                                  // theta: cum-from-top >= 64
        int running = 0;
        for (int base = HB - 1; base >= 0; base -= 32) {
            int bin = base - lane;                   // lane 0 = highest bin
            int cnt = (bin >= 0) ? hist[bin] : 0;
            int pref = cnt;
            #pragma unroll
            for (int o = 1; o < 32; o <<= 1) {
                int nv = __shfl_up_sync(0xffffffffu, pref, o);
                if (lane >= o) pref += nv;
            }
            int tot = __shfl_sync(0xffffffffu, pref, 31);
            if (running + tot >= 64) {
                unsigned msk = __ballot_sync(0xffffffffu, running + pref >= 64);
                int Lm = __ffs(msk) - 1;
                int bstar = base - Lm;
                if (bstar < 0) bstar = 0;
                if (lane == 0) {
                    unsigned tu = (unsigned)bstar << SHIFT;   // bin lower edge
                    float th;
                    if (tu == 0u)               th = -CUDART_INF_F;
                    else if (tu & 0x80000000u)  th = __uint_as_float(tu ^ 0x80000000u);
                    else                        th = __uint_as_float(~tu);
                    shTheta = th;
                }
                break;
            }
            running += tot;
        }
    }
    __syncthreads();
    const float theta = shTheta;

    // ---- flag chunks that can contain a candidate ----
    if (tid < nChunk && chunkMax[tid] >= theta) {
        int q = atomicAdd(&shNFlag, 1);
        flagged[q] = tid;
    }
    __syncthreads();
    const int nFlag = shNFlag;

    // ===== PASS 2: candidates only, flagged chunks via work queue (L2) =====
    while (true) {
        int mc;
        if (lane == 0) mc = atomicAdd(&shQHead, 1);
        mc = __shfl_sync(0xffffffffu, mc, 0);
        if (mc >= nFlag) break;
        const int c = flagged[mc];
        const int base = (c << 8) + (lane << 3);
        float4 q0 = *reinterpret_cast<const float4*>(lpart + base);
        float4 q1 = *reinterpret_cast<const float4*>(lpart + base + 4);
        unsigned w = bm[base >> 5];
        const int sh = base & 31;
        float xs[8] = {q0.x, q0.y, q0.z, q0.w, q1.x, q1.y, q1.z, q1.w};
        #pragma unroll
        for (int j = 0; j < 8; j++) {
            if (!((w >> (sh + j)) & 1u)) {
                float x = xs[j] * invt;
                if (x >= theta) {
                    int q = atomicAdd(&shCand, 1);
                    if (q < PCAP) { candV[q] = x; candI[q] = partBase + base + j; }
                }
            }
        }
    }
    // specials phase B: candidate test
    #pragma unroll
    for (int k = 0; k < WPT1; k++) {
        int wi = tid * WPT1 + k;
        unsigned w = bm[wi];
        int baseTok = wi << 5;
        while (w) {
            int bpos = __ffs(w) - 1; w &= (w - 1);
            int vl = baseTok + bpos;
            float x = spec_val(lpart[vl], partBase + vl, need, s0, s1, s2, s3,
                               stopPenSh, rp, fp, pp, invt, hkey, hcnt);
            if (x >= theta) {
                int q = atomicAdd(&shCand, 1);
                if (q < PCAP) { candV[q] = x; candI[q] = partBase + vl; }
            }
        }
    }
    __syncthreads();

    // ---- exact rank sort of part candidates (value desc, index asc) ----
    const int C = min(shCand, PCAP);
    const int Ntop = min(64, C);
    for (int i = tid; i < C; i += NT1) {
        float vi = candV[i]; int ii = candI[i];
        int r = 0;
        for (int j = 0; j < C; j++) {
            float vj = candV[j];
            if (vj > vi || (vj == vi && candI[j] < ii)) r++;
        }
        if (r < 64) { sortedV[r] = vi; sortedI[r] = ii; }
    }
    __syncthreads();

    // ---- emit part top-64 + partial sum ----
    const int gbase = (b * NPART + p) * 64;
    if (tid < Ntop) { g_pV[gbase + tid] = sortedV[tid]; g_pI[gbase + tid] = sortedI[tid]; }
    if (tid == 0)   { g_pN[b * NPART + p] = Ntop; g_pS[b * NPART + p] = shS; }

    // ===== last-CTA-done handoff =====
    __syncthreads();                                 // all global writes issued
    if (tid == 0) {
        __threadfence();                             // make them visible
        int old = atomicAdd(&g_cnt[b], 1);
        shLast = (old == NPART - 1) ? 1 : 0;
    }
    __syncthreads();
    if (!shLast) return;
    __threadfence();                                 // see other parts' writes

    // ================= MERGE + EPILOGUE (one CTA per row) =================
    {
        const int pp_ = tid >> 6, sl = tid & 63;
        const int n = g_pN[b * NPART + pp_];
        if (sl < n) {
            mV[tid] = g_pV[(b * NPART + pp_) * 64 + sl];
            mI[tid] = g_pI[(b * NPART + pp_) * 64 + sl];
        } else {
            mV[tid] = -CUDART_INF_F;
            mI[tid] = 0x7F000000 + tid;              // unique, sorts last
        }
    }
    __syncthreads();

    // rank-merge 256 -> top 64 (value desc, index asc)
    {
        float vi = mV[tid]; int ii = mI[tid];
        int r = 0;
        #pragma unroll 8
        for (int j = 0; j < NPART * 64; j++) {
            float vj = mV[j];
            if (vj > vi || (vj == vi && mI[j] < ii)) r++;
        }
        if (r < 64) { sortedV[r] = vi; sortedI[r] = ii; }
    }
    __syncthreads();

    // parallel exp of merged top-64 (keeps expf out of the serial chain)
    if (tid < 64) eV[tid] = expf(sortedV[tid]);
    __syncthreads();

    // ---- prefix top-k & top-p (exclusive cumsum, strict <), masked LSE ----
    if (tid == 0) {
        float Sall = 0.0f;
        #pragma unroll
        for (int p2 = 0; p2 < NPART; p2++) Sall += g_pS[b * NPART + p2];
        int totalN = 0;
        #pragma unroll
        for (int p2 = 0; p2 < NPART; p2++) totalN += g_pN[b * NPART + p2];
        const int NtopM = min(64, totalN);
        int ke = top_k[b]; if (ke < 1) ke = V;
        const float tp = top_p[b];
        float c = 0.0f; int nk = 0;
        for (int i = 0; i < NtopM; i++) {
            if (i < ke && c < tp) { nk = i + 1; c += eV[i] / Sall; }
            else break;
        }
        float sum = 0.0f;
        for (int i = 0; i < nk; i++) sum += eV[i];
        shLse = logf(sum);
        shNkept = nk;
    }
    __syncthreads();
    const int nk = shNkept;
    const float lse = shLse;

    // ---- gumbel scores over kept set (parallel noise gather) ----
    if (tid < nk) {
        int idx = sortedI[tid];
        float u = noise[(size_t)b * V + idx];
        float g = -logf(-logf(u));
        scoreV[tid] = sortedV[tid] * invt + g;
    }
    __syncthreads();
    if (tid == 0) {
        int best;
        if (traw < SAMP_EPS) {
            best = sortedI[0];                       // greedy: ties -> lowest index
        } else {
            best = sortedI[0]; float bs = scoreV[0];
            for (int i = 1; i < nk; i++) {
                float sc = scoreV[i]; int ix = sortedI[i];
                if (sc > bs || (sc == bs && ix < best)) { bs = sc; best = ix; }
            }
        }
        out[b] = (float)best;
    }

    // ---- top-L logprobs + indices ----
    float* lpOut = out + B + (size_t)b * L;
    float* ixOut = out + B + (size_t)B * L + (size_t)b * L;
    if (tid < L) {
        if (tid < nk) {
            lpOut[tid] = sortedV[tid] - lse;
            ixOut[tid] = (float)sortedI[tid];
        } else {
            lpOut[tid] = BIG_NEG;                    // exact: -1e30 - lse == -1e30 in f32
        }
    }
    // fill remaining index slots with the smallest non-kept token ids
    // (lax.top_k tie-break: ascending index among equal BIG_NEG values)
    const int needFill = L - nk;
    if (needFill > 0 && tid < 192) {
        int cid = tid;
        bool inKept = false; int less = 0;
        for (int i = 0; i < nk; i++) {
            int si = sortedI[i];
            inKept |= (si == cid);
            less += (si < cid);
        }
        if (!inKept) {
            int rank = cid - less;                   // rank among non-kept ids
            if (rank < needFill) ixOut[nk + rank] = (float)cid;
        }
    }

    // reset row counter for the next graph replay
    __syncthreads();
    if (tid == 0) g_cnt[b] = 0;
}

extern "C" void kernel_launch(void* const* d_in, const int* in_sizes, int n_in,
                              void* d_out, int out_size) {
    const float* logits  = (const float*)d_in[0];
    const int*   prompt  = (const int*)  d_in[1];
    const int*   outtok  = (const int*)  d_in[2];
    const int*   stoptok = (const int*)  d_in[3];
    const int*   mintok  = (const int*)  d_in[4];
    const float* pres    = (const float*)d_in[5];
    const float* freq    = (const float*)d_in[6];
    const float* rep     = (const float*)d_in[7];
    const float* temp    = (const float*)d_in[8];
    const int*   topk    = (const int*)  d_in[9];
    const float* topp    = (const float*)d_in[10];
    const float* noise   = (const float*)d_in[11];

    const int B = in_sizes[4];
    const int V = in_sizes[0] / B;
    const int P = in_sizes[1] / B;
    const int O = in_sizes[2] / B;
    const int S = in_sizes[3] / B;
    const int L = (out_size / B - 1) / 2;   // [sampled(B), logprobs(B,L), indices(B,L)]
    const int Vp = V / NPART;               // 32000 for V=128000 (multiple of 256)

    dim3 grid(NPART, B);
    sampler_kernel<<<grid, NT1>>>(logits, prompt, outtok, stoptok, mintok,
                                  pres, freq, rep, temp, topk, topp, noise,
                                  (float*)d_out, B, V, P, O, S, L, Vp);
}

// round 14
// speedup vs baseline: 1.1956x; 1.1311x over previous
#include <cuda_runtime.h>
#include <cstdint>
#include <math_constants.h>

// Sampler: penalties + temperature + top-k/top-p mask + gumbel sample + top-L logprobs.
// One CTA per row (R10 structure — best measured baseline, 63.6us).
//
// R14 vs R10: the ONLY change is scalarization of the two hot loops. R10-R13
// all used `float xs[8]` locals indexed in an unrolled loop; instruction
// accounting (issue% * cycles => ~60 thread-instr/elem vs ~8 in source, L1 20%
// >> L2/DRAM) indicates ptxas spilled these to local memory. The loops are now
// straight-line scalar code on float4 fields; the bitmap word is shifted once
// per 8-element group so mask tests are constant-bit ANDs. Exp-sum uses a fixed
// pairwise tree (deterministic). All selection logic identical to R10.

#define NT       1024
#define SHIFT    20
#define HB       4096          // ordered-float bins: ordf(x) >> 20
#define CAND_CAP 2048
#define HASH_SZ  512
#define BM_WORDS 4096          // supports V up to 131072
#define WPT      (BM_WORDS / NT)
#define MAXCHUNK 512           // V/256 <= 512
#define BIG_NEG  (-1e30f)
#define SAMP_EPS 1e-5f

__device__ __forceinline__ unsigned ordf(float x) {
    unsigned u = __float_as_uint(x);
    return (u & 0x80000000u) ? ~u : (u | 0x80000000u);
}

__device__ __forceinline__ int hlookup(const int* hkey, const int* hcnt, int tok) {
    unsigned slot = ((unsigned)tok * 2654435761u) & (HASH_SZ - 1);
    while (true) {
        int k = hkey[slot];
        if (k == tok) return hcnt[slot];
        if (k == -1)  return 0;
        slot = (slot + 1) & (HASH_SZ - 1);
    }
}

// Full reference-order transform for a special (bitmap-marked) token:
// stop-min (if needed) -> repetition (if prompt/output member) -> freq/presence
// (if output member) -> temperature.
__device__ __forceinline__ float spec_val(float x, int v, bool need,
    int s0, int s1, int s2, int s3, const int* stopPenSh,
    float rp, float fp, float pp, float invt,
    const int* hkey, const int* hcnt)
{
    bool penal = true;
    if (need) {
        int which = (v == s0) ? 0 : (v == s1) ? 1 : (v == s2) ? 2 : (v == s3) ? 3 : -1;
        if (which >= 0) {
            penal = stopPenSh[which] != 0;   // was it in prompt|output?
            x = fminf(x, BIG_NEG);
        }
    }
    if (penal) {
        x = (x > 0.0f) ? (x / rp) : (x * rp);
        int c = hlookup(hkey, hcnt, v);
        if (c > 0) x -= fp * (float)c + pp;
    }
    return x * invt;
}

__global__ __launch_bounds__(NT) void sampler_kernel(
    const float* __restrict__ logits,
    const int*   __restrict__ prompt_ids,
    const int*   __restrict__ output_ids,
    const int*   __restrict__ stop_ids,
    const int*   __restrict__ min_tokens,
    const float* __restrict__ presence,
    const float* __restrict__ frequency,
    const float* __restrict__ repetition,
    const float* __restrict__ temperature,
    const int*   __restrict__ top_k,
    const float* __restrict__ top_p,
    const float* __restrict__ noise,
    float*       __restrict__ out,
    int B, int V, int P, int O, int S, int L)
{
    __shared__ unsigned bm[BM_WORDS];          // 16KB: prompt|output|(stops if need)
    __shared__ int   hkey[HASH_SZ];            // output-token count hash (4KB)
    __shared__ int   hcnt[HASH_SZ];
    __shared__ int   scratch[HB];              // 16KB, phase-overlaid:
    int*   hist  = scratch;                    //  phase 1: histogram of thread maxes
    float* candV = reinterpret_cast<float*>(scratch);   // phase 2: candidates
    int*   candI = scratch + CAND_CAP;
    __shared__ float chunkMax[MAXCHUNK];       // 2KB (256-elem chunks)
    __shared__ int   flagged[MAXCHUNK];        // 2KB

    __shared__ float sortedV[64];
    __shared__ int   sortedI[64];
    __shared__ float scoreV[64];
    __shared__ float eV[64];
    __shared__ float redf[32];
    __shared__ int   stopPenSh[4];
    __shared__ int   shCand, shNkept, shNFlag, shQHead;
    __shared__ float shS, shLse, shTheta;

    const int b    = blockIdx.x;
    const int tid  = threadIdx.x;
    const int lane = tid & 31;
    const int wid  = tid >> 5;
    const int nChunk = V >> 8;                 // 256-elem chunks (V multiple of 256)

    // ---- init shared ----
    for (int i = tid; i < BM_WORDS; i += NT) bm[i] = 0u;
    for (int i = tid; i < HB;       i += NT) hist[i] = 0;
    for (int i = tid; i < HASH_SZ;  i += NT) { hkey[i] = -1; hcnt[i] = 0; }
    if (tid == 0) { shCand = 0; shNFlag = 0; shQHead = 0; }
    __syncthreads();

    // ---- row params ----
    const bool  need = min_tokens[b] > O;
    const float rp = repetition[b], fp = frequency[b], pp = presence[b];
    const float traw = temperature[b];
    const float t = (traw < SAMP_EPS) ? 1.0f : traw;
    const float invt = 1.0f / t;
    const int s0 = (S > 0) ? stop_ids[(size_t)b * S + 0] : -1;
    const int s1 = (S > 1) ? stop_ids[(size_t)b * S + 1] : -1;
    const int s2 = (S > 2) ? stop_ids[(size_t)b * S + 2] : -1;
    const int s3 = (S > 3) ? stop_ids[(size_t)b * S + 3] : -1;

    // ---- build membership bitmap + output counts ----
    for (int i = tid; i < O; i += NT) {
        int tok = output_ids[(size_t)b * O + i];
        atomicOr(&bm[tok >> 5], 1u << (tok & 31));
        unsigned slot = ((unsigned)tok * 2654435761u) & (HASH_SZ - 1);
        while (true) {
            int old = atomicCAS(&hkey[slot], -1, tok);
            if (old == -1 || old == tok) { atomicAdd(&hcnt[slot], 1); break; }
            slot = (slot + 1) & (HASH_SZ - 1);
        }
    }
    for (int i = tid; i < P; i += NT) {
        int tok = prompt_ids[(size_t)b * P + i];
        atomicOr(&bm[tok >> 5], 1u << (tok & 31));
    }
    __syncthreads();

    // ---- fold stop tokens into bitmap (recording prior membership) ----
    if (tid == 0 && need) {
        int ss[4] = {s0, s1, s2, s3};
        int pen[4];
        #pragma unroll
        for (int k = 0; k < 4; k++)
            pen[k] = (ss[k] >= 0) ? (int)((bm[ss[k] >> 5] >> (ss[k] & 31)) & 1u) : 0;
        #pragma unroll
        for (int k = 0; k < 4; k++) {
            stopPenSh[k] = pen[k];
            if (ss[k] >= 0) bm[ss[k] >> 5] |= 1u << (ss[k] & 31);
        }
    }
    __syncthreads();

    const float* lrow = logits + (size_t)b * V;

    // ===== PASS 1 (only full DRAM pass): thread max + exp-sum + chunk maxes =====
    // Fully scalar body: no local arrays (R10-R13 spilled xs[8] to local mem).
    float mx = -CUDART_INF_F;
    float s  = 0.0f;
    for (int it = 0; ; ++it) {
        const int chunk = (it << 5) + wid;          // warp-uniform
        const int cbase = chunk << 8;
        if (cbase >= V) break;
        const int base = cbase + (lane << 3);
        const float4 q0 = *reinterpret_cast<const float4*>(lrow + base);
        const float4 q1 = *reinterpret_cast<const float4*>(lrow + base + 4);
        const unsigned w = bm[base >> 5] >> (base & 31);   // bits 0..7 for this group

        float x0 = (w &   1u) ? -CUDART_INF_F : q0.x * invt;
        float x1 = (w &   2u) ? -CUDART_INF_F : q0.y * invt;
        float x2 = (w &   4u) ? -CUDART_INF_F : q0.z * invt;
        float x3 = (w &   8u) ? -CUDART_INF_F : q0.w * invt;
        float x4 = (w &  16u) ? -CUDART_INF_F : q1.x * invt;
        float x5 = (w &  32u) ? -CUDART_INF_F : q1.y * invt;
        float x6 = (w &  64u) ? -CUDART_INF_F : q1.z * invt;
        float x7 = (w & 128u) ? -CUDART_INF_F : q1.w * invt;

        // fixed pairwise tree (deterministic), exp(-inf)=0 for masked
        float e01 = __expf(x0) + __expf(x1);
        float e23 = __expf(x2) + __expf(x3);
        float e45 = __expf(x4) + __expf(x5);
        float e67 = __expf(x6) + __expf(x7);
        s += (e01 + e23) + (e45 + e67);

        float im = fmaxf(fmaxf(fmaxf(x0, x1), fmaxf(x2, x3)),
                         fmaxf(fmaxf(x4, x5), fmaxf(x6, x7)));
        mx = fmaxf(mx, im);

        float cm = im;
        #pragma unroll
        for (int o = 16; o; o >>= 1) cm = fmaxf(cm, __shfl_xor_sync(0xffffffffu, cm, o));
        if (lane == 0) chunkMax[chunk] = cm;
    }

    // ---- specials phase A: fold transformed values into thread max + exp-sum ----
    #pragma unroll
    for (int k = 0; k < WPT; k++) {
        int wi = tid * WPT + k;
        unsigned w = bm[wi];
        int baseTok = wi << 5;
        while (w) {
            int bpos = __ffs(w) - 1; w &= (w - 1);
            int v = baseTok + bpos;
            float x = spec_val(lrow[v], v, need, s0, s1, s2, s3, stopPenSh,
                               rp, fp, pp, invt, hkey, hcnt);
            mx = fmaxf(mx, x);
            s += __expf(x);
        }
    }

    // histogram of the 1024 thread-maxes; warp partial sums
    atomicAdd(&hist[ordf(mx) >> SHIFT], 1);
    float ws = s;
    #pragma unroll
    for (int o = 16; o; o >>= 1) ws += __shfl_xor_sync(0xffffffffu, ws, o);
    if (lane == 0) redf[wid] = ws;
    __syncthreads();                                 // hist + redf + chunkMax complete

    if (wid == 0) {                                  // final exp-sum
        float v = redf[lane];
        #pragma unroll
        for (int o = 16; o; o >>= 1) v += __shfl_xor_sync(0xffffffffu, v, o);
        if (lane == 0) shS = v;
    }
    if (wid == 1) {                                  // theta: cum-from-top >= 64
        int running = 0;
        for (int base = HB - 1; base >= 0; base -= 32) {
            int bin = base - lane;                   // lane 0 = highest bin
            int cnt = (bin >= 0) ? hist[bin] : 0;
            int pref = cnt;
            #pragma unroll
            for (int o = 1; o < 32; o <<= 1) {
                int nv = __shfl_up_sync(0xffffffffu, pref, o);
                if (lane >= o) pref += nv;
            }
            int tot = __shfl_sync(0xffffffffu, pref, 31);
            if (running + tot >= 64) {
                unsigned msk = __ballot_sync(0xffffffffu, running + pref >= 64);
                int Lm = __ffs(msk) - 1;
                int bstar = base - Lm;
                if (bstar < 0) bstar = 0;
                if (lane == 0) {
                    unsigned tu = (unsigned)bstar << SHIFT;   // bin lower edge
                    float th;
                    if (tu == 0u)               th = -CUDART_INF_F;
                    else if (tu & 0x80000000u)  th = __uint_as_float(tu ^ 0x80000000u);
                    else                        th = __uint_as_float(~tu);
                    shTheta = th;
                }
                break;
            }
            running += tot;
        }
    }
    __syncthreads();
    const float theta = shTheta;

    // ---- flag chunks that can contain a candidate ----
    if (tid < nChunk && chunkMax[tid] >= theta) {
        int p = atomicAdd(&shNFlag, 1);
        flagged[p] = tid;
    }
    __syncthreads();
    const int nFlag = shNFlag;

    // ===== PASS 2: candidates only, flagged chunks via work queue (L2) =====
    while (true) {
        int mc;
        if (lane == 0) mc = atomicAdd(&shQHead, 1);
        mc = __shfl_sync(0xffffffffu, mc, 0);
        if (mc >= nFlag) break;
        const int c = flagged[mc];
        const int base = (c << 8) + (lane << 3);
        const float4 q0 = *reinterpret_cast<const float4*>(lrow + base);
        const float4 q1 = *reinterpret_cast<const float4*>(lrow + base + 4);
        const unsigned w = bm[base >> 5] >> (base & 31);

        float x;
        #define CAND_TEST(BIT, VAL, OFF)                                   \
            if (!(w & BIT)) {                                              \
                x = (VAL) * invt;                                          \
                if (x >= theta) {                                          \
                    int p = atomicAdd(&shCand, 1);                         \
                    if (p < CAND_CAP) { candV[p] = x; candI[p] = base + OFF; } \
                }                                                          \
            }
        CAND_TEST(  1u, q0.x, 0)
        CAND_TEST(  2u, q0.y, 1)
        CAND_TEST(  4u, q0.z, 2)
        CAND_TEST(  8u, q0.w, 3)
        CAND_TEST( 16u, q1.x, 4)
        CAND_TEST( 32u, q1.y, 5)
        CAND_TEST( 64u, q1.z, 6)
        CAND_TEST(128u, q1.w, 7)
        #undef CAND_TEST
    }
    // specials phase B: candidate test
    #pragma unroll
    for (int k = 0; k < WPT; k++) {
        int wi = tid * WPT + k;
        unsigned w = bm[wi];
        int baseTok = wi << 5;
        while (w) {
            int bpos = __ffs(w) - 1; w &= (w - 1);
            int v = baseTok + bpos;
            float x = spec_val(lrow[v], v, need, s0, s1, s2, s3, stopPenSh,
                               rp, fp, pp, invt, hkey, hcnt);
            if (x >= theta) {
                int p = atomicAdd(&shCand, 1);
                if (p < CAND_CAP) { candV[p] = x; candI[p] = v; }
            }
        }
    }
    __syncthreads();

    // ---- exact rank sort of candidates (value desc, index asc; stable) ----
    const int C = min(shCand, CAND_CAP);
    const int Ntop = min(64, C);
    for (int i = tid; i < C; i += NT) {
        float vi = candV[i]; int ii = candI[i];
        int r = 0;
        for (int j = 0; j < C; j++) {
            float vj = candV[j];
            if (vj > vi || (vj == vi && candI[j] < ii)) r++;
        }
        if (r < 64) { sortedV[r] = vi; sortedI[r] = ii; }
    }
    __syncthreads();

    // parallel exp of top-64 (keeps expf out of the serial chain)
    if (tid < 64) eV[tid] = (tid < Ntop) ? expf(sortedV[tid]) : 0.0f;
    __syncthreads();

    // ---- prefix top-k & top-p (exclusive cumsum, strict <), masked LSE ----
    if (tid == 0) {
        const float Sall = shS;
        int ke = top_k[b]; if (ke < 1) ke = V;
        const float tp = top_p[b];
        float c = 0.0f; int nk = 0;
        for (int i = 0; i < Ntop; i++) {
            if (i < ke && c < tp) { nk = i + 1; c += eV[i] / Sall; }
            else break;
        }
        float sum = 0.0f;
        for (int i = 0; i < nk; i++) sum += eV[i];
        shLse = logf(sum);
        shNkept = nk;
    }
    __syncthreads();
    const int nk = shNkept;
    const float lse = shLse;

    // ---- gumbel scores over kept set (parallel noise gather) ----
    if (tid < nk) {
        int idx = sortedI[tid];
        float u = noise[(size_t)b * V + idx];
        float g = -logf(-logf(u));
        scoreV[tid] = sortedV[tid] * invt + g;
    }
    __syncthreads();
    if (tid == 0) {
        int best;
        if (traw < SAMP_EPS) {
            best = sortedI[0];                       // greedy: ties -> lowest index
        } else {
            best = sortedI[0]; float bs = scoreV[0];
            for (int i = 1; i < nk; i++) {
                float sc = scoreV[i]; int ix = sortedI[i];
                if (sc > bs || (sc == bs && ix < best)) { bs = sc; best = ix; }
            }
        }
        out[b] = (float)best;
    }

    // ---- top-L logprobs + indices ----
    float* lpOut = out + B + (size_t)b * L;
    float* ixOut = out + B + (size_t)B * L + (size_t)b * L;
    if (tid < L) {
        if (tid < nk) {
            lpOut[tid] = sortedV[tid] - lse;
            ixOut[tid] = (float)sortedI[tid];
        } else {
            lpOut[tid] = BIG_NEG;                    // exact: -1e30 - lse == -1e30 in f32
        }
    }
    // fill remaining index slots with the smallest non-kept token ids
    // (lax.top_k tie-break: ascending index among equal BIG_NEG values)
    const int needFill = L - nk;
    if (needFill > 0 && tid < 192) {
        int cid = tid;
        bool inKept = false; int less = 0;
        for (int i = 0; i < nk; i++) {
            int si = sortedI[i];
            inKept |= (si == cid);
            less += (si < cid);
        }
        if (!inKept) {
            int rank = cid - less;                   // rank among non-kept ids
            if (rank < needFill) ixOut[nk + rank] = (float)cid;
        }
    }
}

extern "C" void kernel_launch(void* const* d_in, const int* in_sizes, int n_in,
                              void* d_out, int out_size) {
    const float* logits  = (const float*)d_in[0];
    const int*   prompt  = (const int*)  d_in[1];
    const int*   outtok  = (const int*)  d_in[2];
    const int*   stoptok = (const int*)  d_in[3];
    const int*   mintok  = (const int*)  d_in[4];
    const float* pres    = (const float*)d_in[5];
    const float* freq    = (const float*)d_in[6];
    const float* rep     = (const float*)d_in[7];
    const float* temp    = (const float*)d_in[8];
    const int*   topk    = (const int*)  d_in[9];
    const float* topp    = (const float*)d_in[10];
    const float* noise   = (const float*)d_in[11];

    const int B = in_sizes[4];
    const int V = in_sizes[0] / B;
    const int P = in_sizes[1] / B;
    const int O = in_sizes[2] / B;
    const int S = in_sizes[3] / B;
    const int L = (out_size / B - 1) / 2;   // [sampled(B), logprobs(B,L), indices(B,L)]

    sampler_kernel<<<B, NT>>>(logits, prompt, outtok, stoptok, mintok,
                              pres, freq, rep, temp, topk, topp, noise,
                              (float*)d_out, B, V, P, O, S, L);
}